// round 2
// baseline (speedup 1.0000x reference)
#include <cuda_runtime.h>
#include <cstdint>

#define NN 100000
#define EE 1600000
#define DD 64

// 25.6 MB scratch for aggregated messages (static __device__ -> allocation-free)
__device__ __align__(16) float g_agg[(size_t)NN * DD];

__global__ void zero_kernel() {
    size_t i = (size_t)blockIdx.x * blockDim.x + threadIdx.x;
    float4* p = reinterpret_cast<float4*>(g_agg);
    // grid sized exactly: NN*DD/4 = 1,600,000 threads
    p[i] = make_float4(0.f, 0.f, 0.f, 0.f);
}

// One 16-lane group per edge; each lane handles one float4 chunk of the 64-dim row.
// Leader lane loads src/dst/weight once, broadcasts via shfl (width=16).
// Vector reduction red.global.add.v4.f32 -> 4x fewer L2 atomic ops than scalar.
// NOTE: edge_index arrives as int32 (JAX x64-disabled downgrades the int64 request).
__global__ void scatter_kernel(const float4* __restrict__ x4,
                               const int* __restrict__ ei,
                               const float* __restrict__ ea) {
    unsigned t = blockIdx.x * 256u + threadIdx.x;
    unsigned e = t >> 4;        // edge id  (grid is exact: E*16 == 25,600,000)
    unsigned c = t & 15u;       // float4 chunk within the 64-dim row
    int src = 0, dst = 0;
    float w = 0.f;
    if ((threadIdx.x & 15u) == 0u) {
        src = ei[e];
        dst = ei[EE + e];
        w   = ea[e];
    }
    src = __shfl_sync(0xffffffffu, src, 0, 16);
    dst = __shfl_sync(0xffffffffu, dst, 0, 16);
    w   = __shfl_sync(0xffffffffu, w,   0, 16);

    float4 v = x4[(size_t)src * 16 + c];
    v.x *= w; v.y *= w; v.z *= w; v.w *= w;

    float* p = g_agg + (size_t)dst * DD + (size_t)c * 4;
    asm volatile("red.global.add.v4.f32 [%0], {%1,%2,%3,%4};"
                 :: "l"(p), "f"(v.x), "f"(v.y), "f"(v.z), "f"(v.w)
                 : "memory");
}

// One thread per node. Combined weights [128 k][64 j] transposed into shared
// (k<64: W_rel applied to agg, k>=64: W_root applied to x). Accumulate 64
// outputs as 32 packed f32x2 registers via fma.rn.f32x2 (FFMA2, 2 FLOP-pairs
// per issue slot). Weight loads are broadcast LDS.64 (all lanes same address,
// conflict-free).
__global__ __launch_bounds__(128) void dense_kernel(
        const float4* __restrict__ x4,
        const float* __restrict__ Wrel,
        const float* __restrict__ brel,
        const float* __restrict__ Wroot,
        float* __restrict__ out) {
    __shared__ __align__(16) float sw[128 * 64];
    __shared__ float sb[64];
    int tid = threadIdx.x;
    for (int i = tid; i < 64 * 64; i += 128) {
        int j = i >> 6;       // output index
        int k = i & 63;       // input index
        sw[k * 64 + j]        = Wrel[i];    // i = j*64 + k
        sw[(k + 64) * 64 + j] = Wroot[i];
    }
    if (tid < 64) sb[tid] = brel[tid];
    __syncthreads();

    int n = blockIdx.x * 128 + tid;
    if (n >= NN) return;

    unsigned long long acc[32];
#pragma unroll
    for (int jj = 0; jj < 32; jj++) {
        asm("mov.b64 %0, {%1, %2};"
            : "=l"(acc[jj]) : "f"(sb[2 * jj]), "f"(sb[2 * jj + 1]));
    }

    const float4* arow = reinterpret_cast<const float4*>(g_agg) + (size_t)n * 16;
    const float4* xrow = x4 + (size_t)n * 16;

    // 32 float4 chunks: first 16 from agg (k=0..63), next 16 from x (k=64..127).
    // sw row index = i*4 + s works for both halves by construction.
#pragma unroll 1
    for (int i = 0; i < 32; i++) {
        float4 v = (i < 16) ? arow[i] : xrow[i - 16];
        const unsigned long long* wp =
            reinterpret_cast<const unsigned long long*>(sw + (size_t)i * 4 * 64);
        float vs[4] = {v.x, v.y, v.z, v.w};
#pragma unroll
        for (int s = 0; s < 4; s++) {
            unsigned long long aa;
            asm("mov.b64 %0, {%1, %1};" : "=l"(aa) : "f"(vs[s]));
#pragma unroll
            for (int jj = 0; jj < 32; jj++) {
                asm("fma.rn.f32x2 %0, %1, %2, %0;"
                    : "+l"(acc[jj])
                    : "l"(aa), "l"(wp[s * 32 + jj]));
            }
        }
    }

    float4* orow = reinterpret_cast<float4*>(out) + (size_t)n * 16;
#pragma unroll
    for (int q = 0; q < 16; q++) {
        float a0, a1, a2, a3;
        asm("mov.b64 {%0, %1}, %2;" : "=f"(a0), "=f"(a1) : "l"(acc[2 * q]));
        asm("mov.b64 {%0, %1}, %2;" : "=f"(a2), "=f"(a3) : "l"(acc[2 * q + 1]));
        float4 o;
        o.x = fmaxf(a0, 0.f);
        o.y = fmaxf(a1, 0.f);
        o.z = fmaxf(a2, 0.f);
        o.w = fmaxf(a3, 0.f);
        orow[q] = o;
    }
}

extern "C" void kernel_launch(void* const* d_in, const int* in_sizes, int n_in,
                              void* d_out, int out_size) {
    const float* x     = (const float*)d_in[0];
    const int*   ei    = (const int*)d_in[1];
    const float* ea    = (const float*)d_in[2];
    const float* Wrel  = (const float*)d_in[3];
    const float* brel  = (const float*)d_in[4];
    const float* Wroot = (const float*)d_in[5];
    float*       out   = (float*)d_out;

    zero_kernel<<<6250, 256>>>();                                   // NN*DD/4 / 256
    scatter_kernel<<<100000, 256>>>((const float4*)x, ei, ea);      // E*16 / 256
    dense_kernel<<<(NN + 127) / 128, 128>>>((const float4*)x, Wrel, brel, Wroot, out);
}

// round 3
// speedup vs baseline: 1.2055x; 1.2055x over previous
#include <cuda_runtime.h>
#include <cstdint>

#define NN 100000
#define EE 1600000
#define DD 64
#define SLOTS 64   // max degree capacity; P(deg>64) ~ 1e-18 per node

// Static scratch (allocation-free per harness rules)
__device__ int g_cnt[NN];                                   // 0.4 MB  per-node degree counters
__device__ __align__(16) uint2 g_edata[(size_t)NN * SLOTS]; // 51.2 MB packed {src, w} per dst slot
__device__ __align__(16) float g_agg[(size_t)NN * DD];      // 25.6 MB aggregated messages

__global__ void zero_cnt_kernel() {
    int i = blockIdx.x * 256 + threadIdx.x;
    if (i < NN) g_cnt[i] = 0;
}

// Bin edges by destination: one thread per edge.
// Scalar int atomic assigns the slot; payload {src, w} stored as one STG.64.
__global__ void place_kernel(const int* __restrict__ ei,
                             const float* __restrict__ ea) {
    int e = blockIdx.x * 256 + threadIdx.x;
    if (e >= EE) return;
    int src = ei[e];
    int dst = ei[EE + e];
    float w = ea[e];
    int pos = atomicAdd(&g_cnt[dst], 1);
    if (pos < SLOTS)  // guard (astronomically unlikely overflow -> never corrupt)
        g_edata[(size_t)dst * SLOTS + pos] = make_uint2((unsigned)src, __float_as_uint(w));
}

// Gather-reduce, no atomics: 16 lanes per node, lane c owns float4 chunk c.
// Edge records are broadcast loads (all 16 lanes same address -> 1 wavefront).
__global__ __launch_bounds__(256) void reduce_kernel(const float4* __restrict__ x4) {
    unsigned t = blockIdx.x * 256u + threadIdx.x;   // grid exact: NN*16 = 1.6M
    unsigned n = t >> 4;
    unsigned c = t & 15u;
    if (n >= NN) return;

    int deg = g_cnt[n];
    if (deg > SLOTS) deg = SLOTS;

    const uint2* ebase = g_edata + (size_t)n * SLOTS;
    float4 acc = make_float4(0.f, 0.f, 0.f, 0.f);

    // software pipeline: prefetch next edge record while gathering current x row
    uint2 ed = (deg > 0) ? ebase[0] : make_uint2(0u, 0u);
    for (int i = 0; i < deg; i++) {
        uint2 cur = ed;
        if (i + 1 < deg) ed = ebase[i + 1];
        float w = __uint_as_float(cur.y);
        float4 v = x4[(size_t)cur.x * 16 + c];
        acc.x = fmaf(v.x, w, acc.x);
        acc.y = fmaf(v.y, w, acc.y);
        acc.z = fmaf(v.z, w, acc.z);
        acc.w = fmaf(v.w, w, acc.w);
    }
    reinterpret_cast<float4*>(g_agg)[(size_t)n * 16 + c] = acc;
}

// One thread per node. Combined weights [128 k][64 j] transposed into shared.
// 64 outputs as 32 packed f32x2 accumulators via fma.rn.f32x2.
__global__ __launch_bounds__(128) void dense_kernel(
        const float4* __restrict__ x4,
        const float* __restrict__ Wrel,
        const float* __restrict__ brel,
        const float* __restrict__ Wroot,
        float* __restrict__ out) {
    __shared__ __align__(16) float sw[128 * 64];
    __shared__ float sb[64];
    int tid = threadIdx.x;
    for (int i = tid; i < 64 * 64; i += 128) {
        int j = i >> 6;       // output index
        int k = i & 63;       // input index
        sw[k * 64 + j]        = Wrel[i];    // i = j*64 + k
        sw[(k + 64) * 64 + j] = Wroot[i];
    }
    if (tid < 64) sb[tid] = brel[tid];
    __syncthreads();

    int n = blockIdx.x * 128 + tid;
    if (n >= NN) return;

    unsigned long long acc[32];
#pragma unroll
    for (int jj = 0; jj < 32; jj++) {
        asm("mov.b64 %0, {%1, %2};"
            : "=l"(acc[jj]) : "f"(sb[2 * jj]), "f"(sb[2 * jj + 1]));
    }

    const float4* arow = reinterpret_cast<const float4*>(g_agg) + (size_t)n * 16;
    const float4* xrow = x4 + (size_t)n * 16;

#pragma unroll 1
    for (int i = 0; i < 32; i++) {
        float4 v = (i < 16) ? arow[i] : xrow[i - 16];
        const unsigned long long* wp =
            reinterpret_cast<const unsigned long long*>(sw + (size_t)i * 4 * 64);
        float vs[4] = {v.x, v.y, v.z, v.w};
#pragma unroll
        for (int s = 0; s < 4; s++) {
            unsigned long long aa;
            asm("mov.b64 %0, {%1, %1};" : "=l"(aa) : "f"(vs[s]));
#pragma unroll
            for (int jj = 0; jj < 32; jj++) {
                asm("fma.rn.f32x2 %0, %1, %2, %0;"
                    : "+l"(acc[jj])
                    : "l"(aa), "l"(wp[s * 32 + jj]));
            }
        }
    }

    float4* orow = reinterpret_cast<float4*>(out) + (size_t)n * 16;
#pragma unroll
    for (int q = 0; q < 16; q++) {
        float a0, a1, a2, a3;
        asm("mov.b64 {%0, %1}, %2;" : "=f"(a0), "=f"(a1) : "l"(acc[2 * q]));
        asm("mov.b64 {%0, %1}, %2;" : "=f"(a2), "=f"(a3) : "l"(acc[2 * q + 1]));
        float4 o;
        o.x = fmaxf(a0, 0.f);
        o.y = fmaxf(a1, 0.f);
        o.z = fmaxf(a2, 0.f);
        o.w = fmaxf(a3, 0.f);
        orow[q] = o;
    }
}

extern "C" void kernel_launch(void* const* d_in, const int* in_sizes, int n_in,
                              void* d_out, int out_size) {
    const float* x     = (const float*)d_in[0];
    const int*   ei    = (const int*)d_in[1];
    const float* ea    = (const float*)d_in[2];
    const float* Wrel  = (const float*)d_in[3];
    const float* brel  = (const float*)d_in[4];
    const float* Wroot = (const float*)d_in[5];
    float*       out   = (float*)d_out;

    zero_cnt_kernel<<<(NN + 255) / 256, 256>>>();
    place_kernel<<<(EE + 255) / 256, 256>>>(ei, ea);
    reduce_kernel<<<(NN * 16 + 255) / 256, 256>>>((const float4*)x);
    dense_kernel<<<(NN + 127) / 128, 128>>>((const float4*)x, Wrel, brel, Wroot, out);
}

// round 4
// speedup vs baseline: 1.4834x; 1.2305x over previous
#include <cuda_runtime.h>
#include <cstdint>

#define NN 100000
#define EE 1600000
#define DD 64
#define SLOTS 64   // max degree capacity; P(deg>64) ~ 1e-18 per node

typedef unsigned long long ull;

// Static scratch (allocation-free per harness rules)
__device__ int g_cnt[NN];                                   // 0.4 MB  per-node degree counters
__device__ __align__(16) uint2 g_edata[(size_t)NN * SLOTS]; // 51.2 MB packed {src, w} per dst slot
__device__ __align__(16) float g_agg[(size_t)NN * DD];      // 25.6 MB aggregated messages

__global__ void zero_cnt_kernel() {
    int i = blockIdx.x * 256 + threadIdx.x;
    if (i < NN) g_cnt[i] = 0;
}

// Bin edges by destination: one thread per edge.
__global__ void place_kernel(const int* __restrict__ ei,
                             const float* __restrict__ ea) {
    int e = blockIdx.x * 256 + threadIdx.x;
    if (e >= EE) return;
    int src = ei[e];
    int dst = ei[EE + e];
    float w = ea[e];
    int pos = atomicAdd(&g_cnt[dst], 1);
    if (pos < SLOTS)
        g_edata[(size_t)dst * SLOTS + pos] = make_uint2((unsigned)src, __float_as_uint(w));
}

// Gather-reduce, no atomics: 16 lanes per node, lane c owns float4 chunk c.
__global__ __launch_bounds__(256) void reduce_kernel(const float4* __restrict__ x4) {
    unsigned t = blockIdx.x * 256u + threadIdx.x;
    unsigned n = t >> 4;
    unsigned c = t & 15u;
    if (n >= NN) return;

    int deg = g_cnt[n];
    if (deg > SLOTS) deg = SLOTS;

    const uint2* ebase = g_edata + (size_t)n * SLOTS;
    float4 acc = make_float4(0.f, 0.f, 0.f, 0.f);

    uint2 ed = (deg > 0) ? ebase[0] : make_uint2(0u, 0u);
    for (int i = 0; i < deg; i++) {
        uint2 cur = ed;
        if (i + 1 < deg) ed = ebase[i + 1];
        float w = __uint_as_float(cur.y);
        float4 v = x4[(size_t)cur.x * 16 + c];
        acc.x = fmaf(v.x, w, acc.x);
        acc.y = fmaf(v.y, w, acc.y);
        acc.z = fmaf(v.z, w, acc.z);
        acc.w = fmaf(v.w, w, acc.w);
    }
    reinterpret_cast<float4*>(g_agg)[(size_t)n * 16 + c] = acc;
}

// Dense: [100k x 128] @ [128 x 64] + bias, relu.
// Each thread: 4 nodes x 16 outputs (8 f32x2 pairs). Weight LDS.64 amortized
// over 4 nodes (4x fewer LDS wavefronts than 1-node-per-thread layout).
// Pair index permuted with (p ^ jg) so the 4 jg slabs hit disjoint bank pairs.
__global__ __launch_bounds__(256, 2) void dense_kernel(
        const float4* __restrict__ x4,
        const float* __restrict__ Wrel,
        const float* __restrict__ brel,
        const float* __restrict__ Wroot,
        float* __restrict__ out) {
    __shared__ __align__(16) float sw[128 * 64];
    __shared__ __align__(8)  float sb[64];
    int tid = threadIdx.x;
    for (int i = tid; i < 64 * 64; i += 256) {
        int j = i >> 6;       // output index
        int k = i & 63;       // input index
        sw[k * 64 + j]        = Wrel[i];    // i = j*64 + k
        sw[(k + 64) * 64 + j] = Wroot[i];
    }
    if (tid < 64) sb[tid] = brel[tid];
    __syncthreads();

    int jg = tid & 3;          // output slab: j in [jg*16, jg*16+16)
    int ng = tid >> 2;         // node group (0..63)
    int nbase = blockIdx.x * 256 + ng * 4;

    const ull* swu = reinterpret_cast<const ull*>(sw);   // [128 k][32 pairs]
    const ull* sbu = reinterpret_cast<const ull*>(sb);   // [32 pairs]

    // acc[m][p] holds output pair (jg*8 + (p^jg)) of node nbase+m
    ull acc[4][8];
#pragma unroll
    for (int m = 0; m < 4; m++)
#pragma unroll
        for (int p = 0; p < 8; p++)
            acc[m][p] = sbu[jg * 8 + (p ^ jg)];

    const float4* ar[4];
    const float4* xr[4];
#pragma unroll
    for (int m = 0; m < 4; m++) {
        int n = nbase + m;
        if (n > NN - 1) n = NN - 1;            // tail clamp (stores guarded below)
        ar[m] = reinterpret_cast<const float4*>(g_agg) + (size_t)n * 16;
        xr[m] = x4 + (size_t)n * 16;
    }

#pragma unroll 1
    for (int i = 0; i < 32; i++) {
        float4 v[4];
#pragma unroll
        for (int m = 0; m < 4; m++)
            v[m] = (i < 16) ? ar[m][i] : xr[m][i - 16];
        const ull* wrow = swu + (size_t)i * 4 * 32;      // 4 ks of 32 pairs
#pragma unroll
        for (int s = 0; s < 4; s++) {
            ull w[8];
#pragma unroll
            for (int p = 0; p < 8; p++)
                w[p] = wrow[s * 32 + jg * 8 + (p ^ jg)];
            float vs[4] = {v[0].x, v[0].y, v[0].z, v[0].w};
            // unroll nodes explicitly to index v[m] component s
#pragma unroll
            for (int m = 0; m < 4; m++) {
                float xv = (s == 0) ? v[m].x : (s == 1) ? v[m].y : (s == 2) ? v[m].z : v[m].w;
                ull aa;
                asm("mov.b64 %0, {%1, %1};" : "=l"(aa) : "f"(xv));
#pragma unroll
                for (int p = 0; p < 8; p++) {
                    asm("fma.rn.f32x2 %0, %1, %2, %0;"
                        : "+l"(acc[m][p]) : "l"(aa), "l"(w[p]));
                }
            }
            (void)vs;
        }
    }

#pragma unroll
    for (int m = 0; m < 4; m++) {
        int n = nbase + m;
        if (n >= NN) break;
        float4* orow = reinterpret_cast<float4*>(out) + (size_t)n * 16 + jg * 4;
#pragma unroll
        for (int f = 0; f < 4; f++) {
            float a0, a1, a2, a3;
            asm("mov.b64 {%0, %1}, %2;" : "=f"(a0), "=f"(a1) : "l"(acc[m][(2 * f) ^ jg]));
            asm("mov.b64 {%0, %1}, %2;" : "=f"(a2), "=f"(a3) : "l"(acc[m][(2 * f + 1) ^ jg]));
            float4 o;
            o.x = fmaxf(a0, 0.f);
            o.y = fmaxf(a1, 0.f);
            o.z = fmaxf(a2, 0.f);
            o.w = fmaxf(a3, 0.f);
            orow[f] = o;
        }
    }
}

extern "C" void kernel_launch(void* const* d_in, const int* in_sizes, int n_in,
                              void* d_out, int out_size) {
    const float* x     = (const float*)d_in[0];
    const int*   ei    = (const int*)d_in[1];
    const float* ea    = (const float*)d_in[2];
    const float* Wrel  = (const float*)d_in[3];
    const float* brel  = (const float*)d_in[4];
    const float* Wroot = (const float*)d_in[5];
    float*       out   = (float*)d_out;

    zero_cnt_kernel<<<(NN + 255) / 256, 256>>>();
    place_kernel<<<(EE + 255) / 256, 256>>>(ei, ea);
    reduce_kernel<<<(NN * 16 + 255) / 256, 256>>>((const float4*)x);
    dense_kernel<<<(NN + 255) / 256, 256>>>((const float4*)x, Wrel, brel, Wroot, out);
}

// round 5
// speedup vs baseline: 1.5276x; 1.0298x over previous
#include <cuda_runtime.h>
#include <cstdint>

#define NN 100000
#define EE 1600000
#define DD 64
#define SLOTS 64   // max degree capacity; P(deg>64) ~ 1e-18 per node

typedef unsigned long long ull;

// Static scratch (allocation-free per harness rules)
__device__ int g_cnt[NN];                                   // 0.4 MB  per-node degree counters
__device__ __align__(16) uint2 g_edata[(size_t)NN * SLOTS]; // 51.2 MB packed {src, w} per dst slot
__device__ __align__(16) float g_agg[(size_t)NN * DD];      // 25.6 MB aggregated messages

__global__ void zero_cnt_kernel() {
    int i = blockIdx.x * 256 + threadIdx.x;
    if (i < NN) g_cnt[i] = 0;
}

// Bin edges by destination: one thread per edge.
__global__ void place_kernel(const int* __restrict__ ei,
                             const float* __restrict__ ea) {
    int e = blockIdx.x * 256 + threadIdx.x;
    if (e >= EE) return;
    int src = ei[e];
    int dst = ei[EE + e];
    float w = ea[e];
    int pos = atomicAdd(&g_cnt[dst], 1);
    if (pos < SLOTS)
        g_edata[(size_t)dst * SLOTS + pos] = make_uint2((unsigned)src, __float_as_uint(w));
}

// Gather-reduce, no atomics: 16 lanes per node, lane c owns float4 chunk c.
__global__ __launch_bounds__(256) void reduce_kernel(const float4* __restrict__ x4) {
    unsigned t = blockIdx.x * 256u + threadIdx.x;
    unsigned n = t >> 4;
    unsigned c = t & 15u;
    if (n >= NN) return;

    int deg = g_cnt[n];
    if (deg > SLOTS) deg = SLOTS;

    const uint2* ebase = g_edata + (size_t)n * SLOTS;
    float4 acc = make_float4(0.f, 0.f, 0.f, 0.f);

    uint2 ed = (deg > 0) ? ebase[0] : make_uint2(0u, 0u);
    for (int i = 0; i < deg; i++) {
        uint2 cur = ed;
        if (i + 1 < deg) ed = ebase[i + 1];
        float w = __uint_as_float(cur.y);
        float4 v = x4[(size_t)cur.x * 16 + c];
        acc.x = fmaf(v.x, w, acc.x);
        acc.y = fmaf(v.y, w, acc.y);
        acc.z = fmaf(v.z, w, acc.z);
        acc.w = fmaf(v.w, w, acc.w);
    }
    reinterpret_cast<float4*>(g_agg)[(size_t)n * 16 + c] = acc;
}

// Dense: [100k x 128] @ [128 x 64] + bias, relu.
// Each thread: 8 nodes x 8 outputs (4 f32x2 pairs per node, 64 acc regs).
// Weight LDS.64 amortized over 8 nodes; v-load LDG.128 has only 4 distinct
// addresses per warp (4 node-groups). Pair index permuted with (p ^ (jg>>2))
// so slabs jg and jg+4 (same bank base) hit different bank pairs.
__global__ __launch_bounds__(256, 2) void dense_kernel(
        const float4* __restrict__ x4,
        const float* __restrict__ Wrel,
        const float* __restrict__ brel,
        const float* __restrict__ Wroot,
        float* __restrict__ out) {
    __shared__ __align__(16) float sw[128 * 64];
    __shared__ __align__(8)  float sb[64];
    int tid = threadIdx.x;
    for (int i = tid; i < 64 * 64; i += 256) {
        int j = i >> 6;       // output index
        int k = i & 63;       // input index
        sw[k * 64 + j]        = Wrel[i];    // i = j*64 + k
        sw[(k + 64) * 64 + j] = Wroot[i];
    }
    if (tid < 64) sb[tid] = brel[tid];
    __syncthreads();

    int jg  = tid & 7;         // output slab: j in [jg*8, jg*8+8)
    int jgh = jg >> 2;         // bank-permutation bit
    int ng  = tid >> 3;        // node group (0..31)
    int nbase = blockIdx.x * 256 + ng * 8;

    const ull* swu = reinterpret_cast<const ull*>(sw);   // [128 k][32 pairs]
    const ull* sbu = reinterpret_cast<const ull*>(sb);   // [32 pairs]

    // acc[m][p] holds output pair (jg*4 + (p ^ jgh)) of node nbase+m
    ull acc[8][4];
#pragma unroll
    for (int m = 0; m < 8; m++)
#pragma unroll
        for (int p = 0; p < 4; p++)
            acc[m][p] = sbu[jg * 4 + (p ^ jgh)];

    const float4* ar[8];
    const float4* xr[8];
#pragma unroll
    for (int m = 0; m < 8; m++) {
        int n = nbase + m;
        if (n > NN - 1) n = NN - 1;            // tail clamp (stores guarded below)
        ar[m] = reinterpret_cast<const float4*>(g_agg) + (size_t)n * 16;
        xr[m] = x4 + (size_t)n * 16;
    }

#pragma unroll 1
    for (int i = 0; i < 32; i++) {
        float4 v[8];
#pragma unroll
        for (int m = 0; m < 8; m++)
            v[m] = (i < 16) ? ar[m][i] : xr[m][i - 16];
        const ull* wrow = swu + (size_t)i * 4 * 32;      // 4 ks of 32 pairs
#pragma unroll
        for (int s = 0; s < 4; s++) {
            ull w[4];
#pragma unroll
            for (int p = 0; p < 4; p++)
                w[p] = wrow[s * 32 + jg * 4 + (p ^ jgh)];
#pragma unroll
            for (int m = 0; m < 8; m++) {
                float xv = (s == 0) ? v[m].x : (s == 1) ? v[m].y : (s == 2) ? v[m].z : v[m].w;
                ull aa;
                asm("mov.b64 %0, {%1, %1};" : "=l"(aa) : "f"(xv));
#pragma unroll
                for (int p = 0; p < 4; p++) {
                    asm("fma.rn.f32x2 %0, %1, %2, %0;"
                        : "+l"(acc[m][p]) : "l"(aa), "l"(w[p]));
                }
            }
        }
    }

#pragma unroll
    for (int m = 0; m < 8; m++) {
        int n = nbase + m;
        if (n >= NN) break;
        // outputs jg*8 .. jg*8+7  ->  two float4 stores
        float4* orow = reinterpret_cast<float4*>(out) + (size_t)n * 16 + jg * 2;
#pragma unroll
        for (int f = 0; f < 2; f++) {
            float a0, a1, a2, a3;
            asm("mov.b64 {%0, %1}, %2;" : "=f"(a0), "=f"(a1) : "l"(acc[m][(2 * f) ^ jgh]));
            asm("mov.b64 {%0, %1}, %2;" : "=f"(a2), "=f"(a3) : "l"(acc[m][(2 * f + 1) ^ jgh]));
            float4 o;
            o.x = fmaxf(a0, 0.f);
            o.y = fmaxf(a1, 0.f);
            o.z = fmaxf(a2, 0.f);
            o.w = fmaxf(a3, 0.f);
            orow[f] = o;
        }
    }
}

extern "C" void kernel_launch(void* const* d_in, const int* in_sizes, int n_in,
                              void* d_out, int out_size) {
    const float* x     = (const float*)d_in[0];
    const int*   ei    = (const int*)d_in[1];
    const float* ea    = (const float*)d_in[2];
    const float* Wrel  = (const float*)d_in[3];
    const float* brel  = (const float*)d_in[4];
    const float* Wroot = (const float*)d_in[5];
    float*       out   = (float*)d_out;

    zero_cnt_kernel<<<(NN + 255) / 256, 256>>>();
    place_kernel<<<(EE + 255) / 256, 256>>>(ei, ea);
    reduce_kernel<<<(NN * 16 + 255) / 256, 256>>>((const float4*)x);
    dense_kernel<<<(NN + 255) / 256, 256>>>((const float4*)x, Wrel, brel, Wroot, out);
}

// round 7
// speedup vs baseline: 1.8198x; 1.1913x over previous
#include <cuda_runtime.h>
#include <cuda_bf16.h>
#include <cstdint>

#define NN 100000
#define EE 1600000
#define SLOTS 64

typedef unsigned long long ull;

// Static scratch (allocation-free per harness rules)
__device__ int g_cnt[NN];                                   // per-node degree counters
__device__ __align__(16) uint2 g_edata[(size_t)NN * SLOTS]; // packed {src, w} per dst slot
__device__ __align__(16) float g_y[(size_t)NN * 64];        // x @ W_rel^T
__device__ __align__(16) float g_z[(size_t)NN * 64];        // x @ W_root^T + b

// ---------------- scatter binning ----------------
__global__ void zero_cnt_kernel() {
    int i = blockIdx.x * 256 + threadIdx.x;
    if (i < NN) g_cnt[i] = 0;
}

__global__ void place_kernel(const int* __restrict__ ei,
                             const float* __restrict__ ea) {
    int e = blockIdx.x * 256 + threadIdx.x;
    if (e >= EE) return;
    int src = ei[e];
    int dst = ei[EE + e];
    float w = ea[e];
    int pos = atomicAdd(&g_cnt[dst], 1);
    if (pos < SLOTS)
        g_edata[(size_t)dst * SLOTS + pos] = make_uint2((unsigned)src, __float_as_uint(w));
}

// ---------------- HMMA GEMM: y = x@Wrel^T, z = x@Wroot^T + b ----------------
// C[128 rows x 128 cols] per block = A[128x64] @ Bt[128x64]^T, split-bf16
// compensated (AhiBhi + AhiBlo + AloBhi, fp32 accum). cols 0:64 -> y, 64:128 -> z.

#define SA_HI 0
#define SA_LO 16384
#define SB_HI 32768
#define SB_LO 49152
#define SBIAS 65536
#define SM_SZ (65536 + 256)

__device__ __forceinline__ uint32_t smem_u32(const void* p) {
    uint32_t a;
    asm("{ .reg .u64 t; cvta.to.shared.u64 t, %1; cvt.u32.u64 %0, t; }" : "=r"(a) : "l"(p));
    return a;
}
// pack 4 floats -> 4 bf16 (hi) + 4 bf16 residuals (lo)
__device__ __forceinline__ void split4(float4 v, uint2& H, uint2& L) {
    __nv_bfloat16 h0 = __float2bfloat16(v.x), h1 = __float2bfloat16(v.y);
    __nv_bfloat16 h2 = __float2bfloat16(v.z), h3 = __float2bfloat16(v.w);
    float r0 = v.x - __bfloat162float(h0), r1 = v.y - __bfloat162float(h1);
    float r2 = v.z - __bfloat162float(h2), r3 = v.w - __bfloat162float(h3);
    __nv_bfloat16 l0 = __float2bfloat16(r0), l1 = __float2bfloat16(r1);
    __nv_bfloat16 l2 = __float2bfloat16(r2), l3 = __float2bfloat16(r3);
    H.x = ((uint32_t)__bfloat16_as_ushort(h1) << 16) | __bfloat16_as_ushort(h0);
    H.y = ((uint32_t)__bfloat16_as_ushort(h3) << 16) | __bfloat16_as_ushort(h2);
    L.x = ((uint32_t)__bfloat16_as_ushort(l1) << 16) | __bfloat16_as_ushort(l0);
    L.y = ((uint32_t)__bfloat16_as_ushort(l3) << 16) | __bfloat16_as_ushort(l2);
}

#define LDSM_X4(r0, r1, r2, r3, addr)                                         \
    asm volatile("ldmatrix.sync.aligned.m8n8.x4.shared.b16 {%0,%1,%2,%3}, [%4];" \
                 : "=r"(r0), "=r"(r1), "=r"(r2), "=r"(r3) : "r"(addr))
#define LDSM_X2(r0, r1, addr)                                                 \
    asm volatile("ldmatrix.sync.aligned.m8n8.x2.shared.b16 {%0,%1}, [%2];"    \
                 : "=r"(r0), "=r"(r1) : "r"(addr))
#define MMA_BF16(c0, c1, c2, c3, a0, a1, a2, a3, b0, b1)                      \
    asm volatile("mma.sync.aligned.m16n8k16.row.col.f32.bf16.bf16.f32 "       \
                 "{%0,%1,%2,%3},{%4,%5,%6,%7},{%8,%9},{%0,%1,%2,%3};"         \
                 : "+f"(c0), "+f"(c1), "+f"(c2), "+f"(c3)                     \
                 : "r"(a0), "r"(a1), "r"(a2), "r"(a3), "r"(b0), "r"(b1))

__global__ __launch_bounds__(256) void gemm_kernel(const float4* __restrict__ x4,
                                                   const float* __restrict__ Wrel,
                                                   const float* __restrict__ brel,
                                                   const float* __restrict__ Wroot) {
    extern __shared__ char smem[];
    uint32_t sbase = smem_u32(smem);
    int tid = threadIdx.x;
    int lane = tid & 31, w = tid >> 5;
    int nbase = blockIdx.x * 128;

    // ---- convert A tile: 128 rows of x -> bf16 hi/lo, XOR-swizzled (16B chunks) ----
    {
        int r = tid >> 1, half = tid & 1;
        int n = nbase + r; if (n > NN - 1) n = NN - 1;
        const float4* xr = x4 + (size_t)n * 16;
#pragma unroll
        for (int c = 0; c < 4; c++) {
            int chunk = half * 4 + c;
            uint2 H0, L0, H1, L1;
            split4(xr[chunk * 2], H0, L0);
            split4(xr[chunk * 2 + 1], H1, L1);
            uint32_t off = r * 128 + ((chunk ^ (r & 7)) << 4);
            *reinterpret_cast<uint4*>(smem + SA_HI + off) = make_uint4(H0.x, H0.y, H1.x, H1.y);
            *reinterpret_cast<uint4*>(smem + SA_LO + off) = make_uint4(L0.x, L0.y, L1.x, L1.y);
        }
    }
    // ---- convert B tile: Bt[j][k]; j<64 -> Wrel row j, else Wroot row j-64 ----
    {
        int j = tid >> 1, half = tid & 1;
        const float4* wr = reinterpret_cast<const float4*>(
            (j < 64) ? (Wrel + (size_t)j * 64) : (Wroot + (size_t)(j - 64) * 64));
#pragma unroll
        for (int c = 0; c < 4; c++) {
            int chunk = half * 4 + c;
            uint2 H0, L0, H1, L1;
            split4(wr[chunk * 2], H0, L0);
            split4(wr[chunk * 2 + 1], H1, L1);
            uint32_t off = j * 128 + ((chunk ^ (j & 7)) << 4);
            *reinterpret_cast<uint4*>(smem + SB_HI + off) = make_uint4(H0.x, H0.y, H1.x, H1.y);
            *reinterpret_cast<uint4*>(smem + SB_LO + off) = make_uint4(L0.x, L0.y, L1.x, L1.y);
        }
    }
    if (tid < 64) reinterpret_cast<float*>(smem + SBIAS)[tid] = brel[tid];
    __syncthreads();

    // ---- A fragments for this warp (rows w*16 .. w*16+15), all 4 k-steps ----
    // lane -> (row, chunk-offset) per canonical x4 mapping
    int arow = w * 16 + (lane & 7) + (lane & 8);
    int ach  = lane >> 4;   // 0: k0-7, 1: k8-15
    uint32_t ahi[4][4], alo[4][4];
#pragma unroll
    for (int ks = 0; ks < 4; ks++) {
        uint32_t off = arow * 128 + (((2 * ks + ach) ^ (arow & 7)) << 4);
        LDSM_X4(ahi[ks][0], ahi[ks][1], ahi[ks][2], ahi[ks][3], sbase + SA_HI + off);
        LDSM_X4(alo[ks][0], alo[ks][1], alo[ks][2], alo[ks][3], sbase + SA_LO + off);
    }

    // ---- per n-tile: 4 k-steps x 3 compensated MMAs, then store ----
    int bl = lane & 15;
    int bn = bl & 7;             // local n within tile
    int bch = bl >> 3;           // 0: k0-7, 1: k8-15
    const float* bs = reinterpret_cast<const float*>(smem + SBIAS);

    int row0 = nbase + w * 16 + (lane >> 2);
    int row1 = row0 + 8;
    float2* y2 = reinterpret_cast<float2*>(g_y);
    float2* z2 = reinterpret_cast<float2*>(g_z);

#pragma unroll 1
    for (int nt = 0; nt < 16; nt++) {
        float c0 = 0.f, c1 = 0.f, c2 = 0.f, c3 = 0.f;
        int brow = nt * 8 + bn;
#pragma unroll
        for (int ks = 0; ks < 4; ks++) {
            uint32_t off = brow * 128 + (((2 * ks + bch) ^ (brow & 7)) << 4);
            uint32_t bh0, bh1, bl0, bl1;
            LDSM_X2(bh0, bh1, sbase + SB_HI + off);
            LDSM_X2(bl0, bl1, sbase + SB_LO + off);
            MMA_BF16(c0, c1, c2, c3, ahi[ks][0], ahi[ks][1], ahi[ks][2], ahi[ks][3], bh0, bh1);
            MMA_BF16(c0, c1, c2, c3, ahi[ks][0], ahi[ks][1], ahi[ks][2], ahi[ks][3], bl0, bl1);
            MMA_BF16(c0, c1, c2, c3, alo[ks][0], alo[ks][1], alo[ks][2], alo[ks][3], bh0, bh1);
        }
        int col = nt * 8 + (lane & 3) * 2;      // 0..126 even
        if (nt < 8) {
            if (row0 < NN) y2[(size_t)row0 * 32 + (col >> 1)] = make_float2(c0, c1);
            if (row1 < NN) y2[(size_t)row1 * 32 + (col >> 1)] = make_float2(c2, c3);
        } else {
            int zc = col - 64;
            float b0 = bs[zc], b1 = bs[zc + 1];
            if (row0 < NN) z2[(size_t)row0 * 32 + (zc >> 1)] = make_float2(c0 + b0, c1 + b1);
            if (row1 < NN) z2[(size_t)row1 * 32 + (zc >> 1)] = make_float2(c2 + b0, c3 + b1);
        }
    }
}

// ---------------- fused gather-reduce + relu ----------------
__global__ __launch_bounds__(256) void reduce_out_kernel(float4* __restrict__ out) {
    unsigned t = blockIdx.x * 256u + threadIdx.x;
    unsigned n = t >> 4;
    unsigned c = t & 15u;
    if (n >= NN) return;

    float4 acc = reinterpret_cast<const float4*>(g_z)[(size_t)n * 16 + c];

    int deg = g_cnt[n];
    if (deg > SLOTS) deg = SLOTS;
    const uint2* ebase = g_edata + (size_t)n * SLOTS;
    const float4* y4 = reinterpret_cast<const float4*>(g_y);

    uint2 ed = (deg > 0) ? ebase[0] : make_uint2(0u, 0u);
    for (int i = 0; i < deg; i++) {
        uint2 cur = ed;
        if (i + 1 < deg) ed = ebase[i + 1];
        float w = __uint_as_float(cur.y);
        float4 v = y4[(size_t)cur.x * 16 + c];
        acc.x = fmaf(v.x, w, acc.x);
        acc.y = fmaf(v.y, w, acc.y);
        acc.z = fmaf(v.z, w, acc.z);
        acc.w = fmaf(v.w, w, acc.w);
    }
    acc.x = fmaxf(acc.x, 0.f);
    acc.y = fmaxf(acc.y, 0.f);
    acc.z = fmaxf(acc.z, 0.f);
    acc.w = fmaxf(acc.w, 0.f);
    out[(size_t)n * 16 + c] = acc;
}

extern "C" void kernel_launch(void* const* d_in, const int* in_sizes, int n_in,
                              void* d_out, int out_size) {
    const float* x     = (const float*)d_in[0];
    const int*   ei    = (const int*)d_in[1];
    const float* ea    = (const float*)d_in[2];
    const float* Wrel  = (const float*)d_in[3];
    const float* brel  = (const float*)d_in[4];
    const float* Wroot = (const float*)d_in[5];
    float4*      out   = (float4*)d_out;

    cudaFuncSetAttribute(gemm_kernel, cudaFuncAttributeMaxDynamicSharedMemorySize, SM_SZ);

    zero_cnt_kernel<<<(NN + 255) / 256, 256>>>();
    place_kernel<<<(EE + 255) / 256, 256>>>(ei, ea);
    gemm_kernel<<<(NN + 127) / 128, 256, SM_SZ>>>((const float4*)x, Wrel, brel, Wroot);
    reduce_out_kernel<<<(NN * 16 + 255) / 256, 256>>>(out);
}